// round 15
// baseline (speedup 1.0000x reference)
#include <cuda_runtime.h>
#include <cuda_fp16.h>
#include <cstdint>

#define DM   512
#define LSEQ 2048
#define BSZ  8
#define MTOT (BSZ * LSEQ)      /* 16384 rows */
#define NCH  128
#define CHUNK (LSEQ / NCH)     /* 16 */
#define NSP  16                /* S partial chunks (t < 256) */
#define SD_OFF (BSZ * NCH)     /* sdone flags offset within g_sync */

// Scratch (allocation-free: __device__ globals)
__device__ __half g_h[(size_t)MTOT * DM];           // 16.7 MB (raw GEMM out, fp16)
__device__ __half g_xh[(size_t)MTOT * DM];          // 16.7 MB (X in fp16)
__device__ __half g_wh[(size_t)DM * DM];            // 0.5 MB (W in fp16)
__device__ float  g_psum[MTOT * 4];                 // per-CTA row partial sums
__device__ float  g_psq[MTOT * 4];                  // per-CTA row partial sumsq
__device__ float  g_aggr[BSZ * NCH * DM];           // per-chunk sums (aggregate)
__device__ float  g_incl[BSZ * NCH * DM];           // inclusive prefixes
__device__ float  g_Sre[BSZ * NSP * DM];
__device__ float  g_Sim[BSZ * NSP * DM];
__device__ int    g_sync[BSZ * NCH + BSZ * NSP];    // 0=none,1=aggr,2=incl | sdone

// ===========================================================================
// PTX helpers (arch-portable: sm_80+ path, no 'a' features)
// ===========================================================================
static __device__ __forceinline__ uint32_t smem_u32(const void* p) {
    uint32_t a;
    asm("{ .reg .u64 t; cvta.to.shared.u64 t, %1; cvt.u32.u64 %0, t; }"
        : "=r"(a) : "l"(p));
    return a;
}
static __device__ __forceinline__ void ldsm_x4(uint32_t* r, uint32_t addr) {
    asm volatile("ldmatrix.sync.aligned.m8n8.x4.shared.b16 {%0,%1,%2,%3}, [%4];"
                 : "=r"(r[0]), "=r"(r[1]), "=r"(r[2]), "=r"(r[3]) : "r"(addr));
}
static __device__ __forceinline__ void mma_f16(float* c, const uint32_t* a,
                                               const uint32_t* b) {
    asm volatile(
        "mma.sync.aligned.m16n8k16.row.col.f32.f16.f16.f32 "
        "{%0,%1,%2,%3},{%4,%5,%6,%7},{%8,%9},{%0,%1,%2,%3};"
        : "+f"(c[0]), "+f"(c[1]), "+f"(c[2]), "+f"(c[3])
        : "r"(a[0]), "r"(a[1]), "r"(a[2]), "r"(a[3]), "r"(b[0]), "r"(b[1]));
}
#define CP16(dst, src) \
    asm volatile("cp.async.ca.shared.global [%0], [%1], 16;" \
                 :: "r"(dst), "l"(src) : "memory")
#define CP_COMMIT() asm volatile("cp.async.commit_group;" ::: "memory")
#define CP_WAIT2()  asm volatile("cp.async.wait_group 2;" ::: "memory")

static __device__ __forceinline__ uint32_t pack_h2(__half a, __half b) {
    return ((uint32_t)__half_as_ushort(b) << 16) | __half_as_ushort(a);
}
static __device__ __forceinline__ uint2 cvt4h(float4 v) {
    uint2 r;
    r.x = pack_h2(__float2half_rn(v.x), __float2half_rn(v.y));
    r.y = pack_h2(__float2half_rn(v.z), __float2half_rn(v.w));
    return r;
}
static __device__ __forceinline__ float2 ldcg2(const float* p) {
    float2 v;
    asm volatile("ld.global.cg.v2.f32 {%0,%1}, [%2];"
                 : "=f"(v.x), "=f"(v.y) : "l"(p));
    return v;
}

// ===========================================================================
// Kernel 0: fp32 -> fp16 pre-convert of X and W (pure streaming)
// ===========================================================================
#define N4X ((MTOT * DM) / 4)
#define N4W ((DM * DM) / 4)
__global__ __launch_bounds__(256)
void cvt_kernel(const float* __restrict__ X, const float* __restrict__ W)
{
    const int idx = blockIdx.x * 256 + threadIdx.x;
    const int stride = gridDim.x * 256;
    for (int i = idx; i < N4X + N4W; i += stride) {
        if (i < N4X) {
            const float4 v = *(const float4*)(X + (size_t)i * 4);
            *(uint2*)(g_xh + (size_t)i * 4) = cvt4h(v);
        } else {
            const int j = i - N4X;
            const float4 v = *(const float4*)(W + (size_t)j * 4);
            *(uint2*)(g_wh + (size_t)j * 4) = cvt4h(v);
        }
    }
}

// ===========================================================================
// Kernel 1: fp16 mma.sync GEMM, cp.async 4-stage pipeline.
// H = X W^T + bias (stored fp16) + per-CTA LN partial stats. (unchanged)
// ===========================================================================
#define KC       32
#define NKC      (DM / KC)
#define ROW_B    80
#define HTILE_B  (128 * ROW_B)
#define STAGE_B  (2 * HTILE_B)
#define NSTG     4
#define SMEM_G   (NSTG * STAGE_B)          /* 81920 B per CTA */

__global__ __launch_bounds__(256, 2)
void gemm_mma_kernel(const float* __restrict__ bias)
{
    extern __shared__ char smem[];
    const uint32_t sb = smem_u32(smem);
    const int tid  = threadIdx.x;
    const int wid  = tid >> 5;
    const int lane = tid & 31;
    const int bm   = blockIdx.y * 128;
    const int bn   = blockIdx.x * 128;
    const int wm   = (wid & 1) * 64;
    const int wn   = (wid >> 1) * 32;

    const int p0 = tid * 2;
    const int r0 = p0 >> 2, c0 = p0 & 3;
    const int p1 = p0 + 1;
    const int r1 = p1 >> 2, c1 = p1 & 3;

    const __half* Xb = g_xh + (size_t)bm * DM;
    const __half* Wb = g_wh + (size_t)bn * DM;

    auto issue_stage = [&](int kc, int stg) {
        const uint32_t sA = sb + stg * STAGE_B;
        const uint32_t sB = sA + HTILE_B;
        const int ko = kc * KC;
        CP16(sA + r0 * ROW_B + c0 * 16, Xb + (size_t)r0 * DM + ko + c0 * 8);
        CP16(sA + r1 * ROW_B + c1 * 16, Xb + (size_t)r1 * DM + ko + c1 * 8);
        CP16(sB + r0 * ROW_B + c0 * 16, Wb + (size_t)r0 * DM + ko + c0 * 8);
        CP16(sB + r1 * ROW_B + c1 * 16, Wb + (size_t)r1 * DM + ko + c1 * 8);
    };

    float acc[4][4][4];
#pragma unroll
    for (int mt = 0; mt < 4; ++mt)
#pragma unroll
        for (int nt = 0; nt < 4; ++nt)
#pragma unroll
            for (int q = 0; q < 4; ++q) acc[mt][nt][q] = 0.0f;

    issue_stage(0, 0); CP_COMMIT();
    issue_stage(1, 1); CP_COMMIT();
    issue_stage(2, 2); CP_COMMIT();

    const int a_lr  = lane & 15;
    const int a_lk  = (lane >> 4) * 8;
    const int b_nr  = ((lane >> 4) & 1) * 8 + (lane & 7);
    const int b_lk  = ((lane >> 3) & 1) * 8;

    for (int kc = 0; kc < NKC; ++kc) {
        CP_WAIT2();
        __syncthreads();
        if (kc + 3 < NKC) issue_stage(kc + 3, (kc + 3) % NSTG);
        CP_COMMIT();

        const uint32_t sA = sb + (kc % NSTG) * STAGE_B;
        const uint32_t sB = sA + HTILE_B;

#pragma unroll
        for (int ks = 0; ks < 2; ++ks) {
            uint32_t ah[4][4], bf[4][2];
#pragma unroll
            for (int mt = 0; mt < 4; ++mt) {
                const uint32_t aaddr = sA +
                    (uint32_t)((wm + mt * 16 + a_lr) * ROW_B + (ks * 16 + a_lk) * 2);
                ldsm_x4(ah[mt], aaddr);
            }
#pragma unroll
            for (int np = 0; np < 2; ++np) {
                const uint32_t baddr = sB +
                    (uint32_t)((wn + np * 16 + b_nr) * ROW_B + (ks * 16 + b_lk) * 2);
                uint32_t t[4];
                ldsm_x4(t, baddr);
                bf[np * 2][0] = t[0]; bf[np * 2][1] = t[1];
                bf[np * 2 + 1][0] = t[2]; bf[np * 2 + 1][1] = t[3];
            }
#pragma unroll
            for (int mt = 0; mt < 4; ++mt)
#pragma unroll
                for (int nt = 0; nt < 4; ++nt)
                    mma_f16(acc[mt][nt], ah[mt], bf[nt]);
        }
    }

    const int gq = lane >> 2;
    const int r2 = (lane & 3) * 2;
    float2 bv[4];
#pragma unroll
    for (int nt = 0; nt < 4; ++nt)
        bv[nt] = *(const float2*)(bias + bn + wn + nt * 8 + r2);

    float2* red = (float2*)smem;
#pragma unroll
    for (int mt = 0; mt < 4; ++mt) {
        const int row0 = bm + wm + mt * 16 + gq;
        float sA = 0.f, qA = 0.f, sB = 0.f, qB = 0.f;
#pragma unroll
        for (int nt = 0; nt < 4; ++nt) {
            const int col = bn + wn + nt * 8 + r2;
            const float v0x = acc[mt][nt][0] + bv[nt].x;
            const float v0y = acc[mt][nt][1] + bv[nt].y;
            const float v1x = acc[mt][nt][2] + bv[nt].x;
            const float v1y = acc[mt][nt][3] + bv[nt].y;
            *(__half2*)(g_h + (size_t)row0 * DM + col) = __floats2half2_rn(v0x, v0y);
            *(__half2*)(g_h + (size_t)(row0 + 8) * DM + col) = __floats2half2_rn(v1x, v1y);
            sA += v0x + v0y; qA += v0x * v0x + v0y * v0y;
            sB += v1x + v1y; qB += v1x * v1x + v1y * v1y;
        }
#pragma unroll
        for (int o = 1; o <= 2; o <<= 1) {
            sA += __shfl_xor_sync(0xFFFFFFFFu, sA, o);
            qA += __shfl_xor_sync(0xFFFFFFFFu, qA, o);
            sB += __shfl_xor_sync(0xFFFFFFFFu, sB, o);
            qB += __shfl_xor_sync(0xFFFFFFFFu, qB, o);
        }
        if ((lane & 3) == 0) {
            const int lr = wm + mt * 16 + gq;
            red[(wid >> 1) * 128 + lr]     = make_float2(sA, qA);
            red[(wid >> 1) * 128 + lr + 8] = make_float2(sB, qB);
        }
    }
    __syncthreads();
    if (tid < 128) {
        float s = 0.f, q = 0.f;
#pragma unroll
        for (int ns = 0; ns < 4; ++ns) {
            const float2 v = red[ns * 128 + tid];
            s += v.x; q += v.y;
        }
        g_psum[(size_t)(bm + tid) * 4 + blockIdx.x] = s;
        g_psq [(size_t)(bm + tid) * 4 + blockIdx.x] = q;
    }
}

// ===========================================================================
// Kernel 2 (single-pass fused): LN stats + chunk sums + decoupled-lookback
// prefix + output + tail. grid = (NCH=128, BSZ), 256 threads (channel pairs).
// Lookback safety: predecessors (same b, smaller c) have smaller linear block
// index and are scheduled no later.
// ===========================================================================
__global__ __launch_bounds__(256)
void pass_fused_kernel(float* __restrict__ Y,
                       const float* __restrict__ Are, const float* __restrict__ Aim,
                       const float* __restrict__ Bre, const float* __restrict__ Bim,
                       const float* __restrict__ Cre, const float* __restrict__ Cim,
                       const float* __restrict__ Dre,
                       const float* __restrict__ gamma, const float* __restrict__ beta)
{
    __shared__ float s_mu[CHUNK], s_rs[CHUNK];
    __shared__ int   s_st;
    const int tid = threadIdx.x;
    const int c = blockIdx.x;
    const int b = blockIdx.y;
    const size_t row0 = (size_t)b * LSEQ + (size_t)c * CHUNK;

    // --- LN stats from GEMM partials ---
    if (tid < CHUNK) {
        const size_t gr = row0 + tid;
        float s = 0.f, q = 0.f;
#pragma unroll
        for (int ns = 0; ns < 4; ++ns) {
            s += g_psum[gr * 4 + ns];
            q += g_psq[gr * 4 + ns];
        }
        const float mu   = s * (1.0f / DM);
        const float var  = q * (1.0f / DM) - mu * mu;
        s_mu[tid] = mu;
        s_rs[tid] = rsqrtf(var + 1e-5f);
    }
    __syncthreads();

    const int d = tid * 2;
    const float2 gd = *(const float2*)(gamma + d);
    const float2 bd = *(const float2*)(beta + d);

    // --- prefetch chunk column + local sums of normalized h ---
    __half2 hvr[CHUNK];
#pragma unroll
    for (int i = 0; i < CHUNK; ++i)
        hvr[i] = *(const __half2*)(g_h + row0 * DM + d + (size_t)i * DM);

    float hn0[CHUNK], hn1[CHUNK];
    float2 s = make_float2(0.f, 0.f);
#pragma unroll
    for (int i = 0; i < CHUNK; ++i) {
        const float2 hv = __half22float2(hvr[i]);
        hn0[i] = (hv.x - s_mu[i]) * s_rs[i] * gd.x + bd.x;
        hn1[i] = (hv.y - s_mu[i]) * s_rs[i] * gd.y + bd.y;
        s.x += hn0[i]; s.y += hn1[i];
    }

    // --- S partials (c < NSP), rotated by A^(16c) ---
    if (c < NSP) {
        const float2 are = *(const float2*)(Are + d);
        const float2 aim = *(const float2*)(Aim + d);
        float pre0 = 1.f, pim0 = 0.f, Sre0 = 0.f, Sim0 = 0.f;
        float pre1 = 1.f, pim1 = 0.f, Sre1 = 0.f, Sim1 = 0.f;
#pragma unroll
        for (int i = 0; i < CHUNK; ++i) {
            Sre0 = fmaf(pre0, hn0[i], Sre0);  Sim0 = fmaf(pim0, hn0[i], Sim0);
            Sre1 = fmaf(pre1, hn1[i], Sre1);  Sim1 = fmaf(pim1, hn1[i], Sim1);
            float nr = pre0 * are.x - pim0 * aim.x;
            float ni = pre0 * aim.x + pim0 * are.x;
            pre0 = nr; pim0 = ni;
            nr = pre1 * are.y - pim1 * aim.y;
            ni = pre1 * aim.y + pim1 * are.y;
            pre1 = nr; pim1 = ni;
        }
        float wre0 = 1.f, wim0 = 0.f, wre1 = 1.f, wim1 = 0.f;
        if (c > 0) {
            float t0r = are.x, t0i = aim.x, t1r = are.y, t1i = aim.y;
#pragma unroll
            for (int k = 0; k < 4; ++k) {
                float nr = t0r * t0r - t0i * t0i, ni = 2.f * t0r * t0i;
                t0r = nr; t0i = ni;
                nr = t1r * t1r - t1i * t1i; ni = 2.f * t1r * t1i;
                t1r = nr; t1i = ni;
            }
            for (int j = 0; j < c; ++j) {
                float nr = wre0 * t0r - wim0 * t0i, ni = wre0 * t0i + wim0 * t0r;
                wre0 = nr; wim0 = ni;
                nr = wre1 * t1r - wim1 * t1i; ni = wre1 * t1i + wim1 * t1r;
                wre1 = nr; wim1 = ni;
            }
        }
        float2 oSr, oSi;
        oSr.x = Sre0 * wre0 - Sim0 * wim0;  oSi.x = Sre0 * wim0 + Sim0 * wre0;
        oSr.y = Sre1 * wre1 - Sim1 * wim1;  oSi.y = Sre1 * wim1 + Sim1 * wre1;
        *(float2*)(g_Sre + ((size_t)b * NSP + c) * DM + d) = oSr;
        *(float2*)(g_Sim + ((size_t)b * NSP + c) * DM + d) = oSi;
    }

    // --- publish aggregate (and sdone for S blocks) ---
    *(float2*)(g_aggr + ((size_t)b * NCH + c) * DM + d) = s;
    __threadfence();
    __syncthreads();
    if (tid == 0) {
        atomicExch(&g_sync[b * NCH + c], 1);
        if (c < NSP) atomicExch(&g_sync[SD_OFF + b * NSP + c], 1);
    }

    // --- decoupled lookback: exclusive prefix ex ---
    float2 ex = make_float2(0.f, 0.f);
    for (int pc = c - 1; pc >= 0; ) {
        if (tid == 0) {
            int st;
            do { st = atomicAdd(&g_sync[b * NCH + pc], 0); } while (st == 0);
            s_st = st;
        }
        __syncthreads();
        const int st = s_st;
        __threadfence();
        if (st == 2) {
            const float2 v = ldcg2(g_incl + ((size_t)b * NCH + pc) * DM + d);
            ex.x += v.x; ex.y += v.y;
            break;
        } else {
            const float2 v = ldcg2(g_aggr + ((size_t)b * NCH + pc) * DM + d);
            ex.x += v.x; ex.y += v.y;
            --pc;
        }
        __syncthreads();
    }

    // --- publish inclusive ---
    float2 inc;
    inc.x = ex.x + s.x;  inc.y = ex.y + s.y;
    *(float2*)(g_incl + ((size_t)b * NCH + c) * DM + d) = inc;
    __threadfence();
    __syncthreads();
    if (tid == 0) atomicExch(&g_sync[b * NCH + c], 2);

    // --- tail term (last chunk): wait for S partials ---
    float t0[CHUNK], t1[CHUNK];
    bool tail = (c == NCH - 1);
    if (tail) {
        if (tid < NSP) {
            while (atomicAdd(&g_sync[SD_OFF + b * NSP + tid], 0) == 0) {}
        }
        __syncthreads();
        __threadfence();
        const float2 are = *(const float2*)(Are + d);
        const float2 aim = *(const float2*)(Aim + d);
        const float2 bre = *(const float2*)(Bre + d);
        const float2 bim = *(const float2*)(Bim + d);
        const float2 cre = *(const float2*)(Cre + d);
        const float2 cim = *(const float2*)(Cim + d);
        const float bcre0 = bre.x * cre.x - bim.x * cim.x;
        const float bcim0 = bre.x * cim.x + bim.x * cre.x;
        const float bcre1 = bre.y * cre.y - bim.y * cim.y;
        const float bcim1 = bre.y * cim.y + bim.y * cre.y;
        float2 Sre = make_float2(0.f, 0.f), Sim = make_float2(0.f, 0.f);
#pragma unroll
        for (int j = 0; j < NSP; ++j) {
            const float2 vr = ldcg2(g_Sre + ((size_t)b * NSP + j) * DM + d);
            const float2 vi = ldcg2(g_Sim + ((size_t)b * NSP + j) * DM + d);
            Sre.x += vr.x; Sre.y += vr.y;
            Sim.x += vi.x; Sim.y += vi.y;
        }
        float q0r = 1.f, q0i = 0.f, q1r = 1.f, q1i = 0.f;
#pragma unroll
        for (int i = CHUNK - 1; i >= 0; --i) {
            const float z0r = q0r * Sre.x - q0i * Sim.x;
            const float z0i = q0r * Sim.x + q0i * Sre.x;
            const float z1r = q1r * Sre.y - q1i * Sim.y;
            const float z1i = q1r * Sim.y + q1i * Sre.y;
            t0[i] = bcre0 * z0r - bcim0 * z0i;
            t1[i] = bcre1 * z1r - bcim1 * z1i;
            float nr = q0r * are.x - q0i * aim.x, ni = q0r * aim.x + q0i * are.x;
            q0r = nr; q0i = ni;
            nr = q1r * are.y - q1i * aim.y; ni = q1r * aim.y + q1i * are.y;
            q1r = nr; q1i = ni;
        }
    }

    // --- outputs ---
    const size_t base = row0 * DM + d;
    const float2 dre = *(const float2*)(Dre + d);
    float2 run = ex;
    if (!tail) {
#pragma unroll
        for (int i = 0; i < CHUNK; ++i) {
            run.x += hn0[i]; run.y += hn1[i];
            float2 out;
            out.x = fmaf(dre.x, run.x, hn0[i]);
            out.y = fmaf(dre.y, run.y, hn1[i]);
            *(float2*)(Y + base + (size_t)i * DM) = out;
        }
    } else {
#pragma unroll
        for (int i = 0; i < CHUNK; ++i) {
            run.x += hn0[i]; run.y += hn1[i];
            float2 out;
            out.x = fmaf(dre.x, run.x, hn0[i]) + t0[i];
            out.y = fmaf(dre.y, run.y, hn1[i]) + t1[i];
            *(float2*)(Y + base + (size_t)i * DM) = out;
        }
    }
}

// ---------------------------------------------------------------------------
extern "C" void kernel_launch(void* const* d_in, const int* in_sizes, int n_in,
                              void* d_out, int out_size)
{
    const float* x    = (const float*)d_in[0];
    const float* Are  = (const float*)d_in[1];
    const float* Aim  = (const float*)d_in[2];
    const float* Bre  = (const float*)d_in[3];
    const float* Bim  = (const float*)d_in[4];
    const float* Cre  = (const float*)d_in[5];
    const float* Cim  = (const float*)d_in[6];
    const float* Dre  = (const float*)d_in[7];
    const float* W    = (const float*)d_in[9];
    const float* bias = (const float*)d_in[10];
    const float* gamma= (const float*)d_in[11];
    const float* beta = (const float*)d_in[12];
    float* out = (float*)d_out;

    // reset lookback flags (graph-capturable memset node)
    void* syncp = nullptr;
    cudaGetSymbolAddress(&syncp, g_sync);
    cudaMemsetAsync(syncp, 0, sizeof(int) * (BSZ * NCH + BSZ * NSP));

    cudaFuncSetAttribute(gemm_mma_kernel,
                         cudaFuncAttributeMaxDynamicSharedMemorySize, SMEM_G);
    cvt_kernel<<<1184, 256>>>(x, W);
    gemm_mma_kernel<<<dim3(DM / 128, MTOT / 128), 256, SMEM_G>>>(bias);
    pass_fused_kernel<<<dim3(NCH, BSZ), 256>>>(out, Are, Aim, Bre, Bim,
                                               Cre, Cim, Dre, gamma, beta);
}

// round 16
// speedup vs baseline: 1.5308x; 1.5308x over previous
#include <cuda_runtime.h>
#include <cuda_fp16.h>
#include <cstdint>

#define DM   512
#define LSEQ 2048
#define BSZ  8
#define MTOT (BSZ * LSEQ)      /* 16384 rows */
#define NCH  128
#define CHUNK (LSEQ / NCH)     /* 16 */
#define NSP  16                /* S partial chunks (t < 256) */

// Scratch (allocation-free: __device__ globals)
__device__ __half g_h[(size_t)MTOT * DM];           // 16.7 MB (raw GEMM out, fp16)
__device__ __half g_xh[(size_t)MTOT * DM];          // 16.7 MB (X in fp16)
__device__ __half g_wh[(size_t)DM * DM];            // 0.5 MB (W in fp16)
__device__ float  g_psum[MTOT * 4];                 // per-CTA row partial sums
__device__ float  g_psq[MTOT * 4];                  // per-CTA row partial sumsq
__device__ float  g_mu[MTOT];
__device__ float  g_rs[MTOT];
__device__ float  g_csum[BSZ * NCH * DM];           // chunk sums -> excl. prefix
__device__ float  g_Sre[BSZ * NSP * DM];
__device__ float  g_Sim[BSZ * NSP * DM];

// ===========================================================================
// PTX helpers (arch-portable: sm_80+ path, no 'a' features)
// ===========================================================================
static __device__ __forceinline__ uint32_t smem_u32(const void* p) {
    uint32_t a;
    asm("{ .reg .u64 t; cvta.to.shared.u64 t, %1; cvt.u32.u64 %0, t; }"
        : "=r"(a) : "l"(p));
    return a;
}
static __device__ __forceinline__ void ldsm_x4(uint32_t* r, uint32_t addr) {
    asm volatile("ldmatrix.sync.aligned.m8n8.x4.shared.b16 {%0,%1,%2,%3}, [%4];"
                 : "=r"(r[0]), "=r"(r[1]), "=r"(r[2]), "=r"(r[3]) : "r"(addr));
}
static __device__ __forceinline__ void mma_f16(float* c, const uint32_t* a,
                                               const uint32_t* b) {
    asm volatile(
        "mma.sync.aligned.m16n8k16.row.col.f32.f16.f16.f32 "
        "{%0,%1,%2,%3},{%4,%5,%6,%7},{%8,%9},{%0,%1,%2,%3};"
        : "+f"(c[0]), "+f"(c[1]), "+f"(c[2]), "+f"(c[3])
        : "r"(a[0]), "r"(a[1]), "r"(a[2]), "r"(a[3]), "r"(b[0]), "r"(b[1]));
}
#define CP16(dst, src) \
    asm volatile("cp.async.ca.shared.global [%0], [%1], 16;" \
                 :: "r"(dst), "l"(src) : "memory")
#define CP_COMMIT() asm volatile("cp.async.commit_group;" ::: "memory")
#define CP_WAIT2()  asm volatile("cp.async.wait_group 2;" ::: "memory")

static __device__ __forceinline__ uint32_t pack_h2(__half a, __half b) {
    return ((uint32_t)__half_as_ushort(b) << 16) | __half_as_ushort(a);
}
static __device__ __forceinline__ uint2 cvt4h(float4 v) {
    uint2 r;
    r.x = pack_h2(__float2half_rn(v.x), __float2half_rn(v.y));
    r.y = pack_h2(__float2half_rn(v.z), __float2half_rn(v.w));
    return r;
}

// ===========================================================================
// Kernel 0: fp32 -> fp16 pre-convert of X and W.
// Exact grid (one float4 per thread), streaming stores for X.
// ===========================================================================
#define N4X ((MTOT * DM) / 4)               /* 2,097,152 */
#define N4W ((DM * DM) / 4)                 /* 65,536 */
#define N4T (N4X + N4W)                     /* 2,162,688 = 8448 * 256 */
__global__ __launch_bounds__(256)
void cvt_kernel(const float* __restrict__ X, const float* __restrict__ W)
{
    const int i = blockIdx.x * 256 + threadIdx.x;
    if (i < N4X) {
        const float4 v = *(const float4*)(X + (size_t)i * 4);
        const uint2 h = cvt4h(v);
        __stcs((uint2*)(g_xh + (size_t)i * 4), h);
    } else {
        const int j = i - N4X;
        const float4 v = *(const float4*)(W + (size_t)j * 4);
        *(uint2*)(g_wh + (size_t)j * 4) = cvt4h(v);
    }
}

// ===========================================================================
// Kernel 1: fp16 mma.sync GEMM, cp.async 4-stage pipeline.
// H = X W^T + bias (stored fp16) + per-CTA LN partial stats (deterministic).
// CTA 128x128, 256 thr / 8 warps, 2 CTAs/SM.
// ===========================================================================
#define KC       32
#define NKC      (DM / KC)
#define ROW_B    80
#define HTILE_B  (128 * ROW_B)
#define STAGE_B  (2 * HTILE_B)
#define NSTG     4
#define SMEM_G   (NSTG * STAGE_B)          /* 81920 B per CTA */

__global__ __launch_bounds__(256, 2)
void gemm_mma_kernel(const float* __restrict__ bias)
{
    extern __shared__ char smem[];
    const uint32_t sb = smem_u32(smem);
    const int tid  = threadIdx.x;
    const int wid  = tid >> 5;
    const int lane = tid & 31;
    const int bm   = blockIdx.y * 128;
    const int bn   = blockIdx.x * 128;
    const int wm   = (wid & 1) * 64;
    const int wn   = (wid >> 1) * 32;

    const int p0 = tid * 2;
    const int r0 = p0 >> 2, c0 = p0 & 3;
    const int p1 = p0 + 1;
    const int r1 = p1 >> 2, c1 = p1 & 3;

    const __half* Xb = g_xh + (size_t)bm * DM;
    const __half* Wb = g_wh + (size_t)bn * DM;

    auto issue_stage = [&](int kc, int stg) {
        const uint32_t sA = sb + stg * STAGE_B;
        const uint32_t sB = sA + HTILE_B;
        const int ko = kc * KC;
        CP16(sA + r0 * ROW_B + c0 * 16, Xb + (size_t)r0 * DM + ko + c0 * 8);
        CP16(sA + r1 * ROW_B + c1 * 16, Xb + (size_t)r1 * DM + ko + c1 * 8);
        CP16(sB + r0 * ROW_B + c0 * 16, Wb + (size_t)r0 * DM + ko + c0 * 8);
        CP16(sB + r1 * ROW_B + c1 * 16, Wb + (size_t)r1 * DM + ko + c1 * 8);
    };

    float acc[4][4][4];
#pragma unroll
    for (int mt = 0; mt < 4; ++mt)
#pragma unroll
        for (int nt = 0; nt < 4; ++nt)
#pragma unroll
            for (int q = 0; q < 4; ++q) acc[mt][nt][q] = 0.0f;

    issue_stage(0, 0); CP_COMMIT();
    issue_stage(1, 1); CP_COMMIT();
    issue_stage(2, 2); CP_COMMIT();

    const int a_lr  = lane & 15;
    const int a_lk  = (lane >> 4) * 8;
    const int b_nr  = ((lane >> 4) & 1) * 8 + (lane & 7);
    const int b_lk  = ((lane >> 3) & 1) * 8;

    for (int kc = 0; kc < NKC; ++kc) {
        CP_WAIT2();
        __syncthreads();
        if (kc + 3 < NKC) issue_stage(kc + 3, (kc + 3) % NSTG);
        CP_COMMIT();

        const uint32_t sA = sb + (kc % NSTG) * STAGE_B;
        const uint32_t sB = sA + HTILE_B;

#pragma unroll
        for (int ks = 0; ks < 2; ++ks) {
            uint32_t ah[4][4], bf[4][2];
#pragma unroll
            for (int mt = 0; mt < 4; ++mt) {
                const uint32_t aaddr = sA +
                    (uint32_t)((wm + mt * 16 + a_lr) * ROW_B + (ks * 16 + a_lk) * 2);
                ldsm_x4(ah[mt], aaddr);
            }
#pragma unroll
            for (int np = 0; np < 2; ++np) {
                const uint32_t baddr = sB +
                    (uint32_t)((wn + np * 16 + b_nr) * ROW_B + (ks * 16 + b_lk) * 2);
                uint32_t t[4];
                ldsm_x4(t, baddr);
                bf[np * 2][0] = t[0]; bf[np * 2][1] = t[1];
                bf[np * 2 + 1][0] = t[2]; bf[np * 2 + 1][1] = t[3];
            }
#pragma unroll
            for (int mt = 0; mt < 4; ++mt)
#pragma unroll
                for (int nt = 0; nt < 4; ++nt)
                    mma_f16(acc[mt][nt], ah[mt], bf[nt]);
        }
    }

    const int gq = lane >> 2;
    const int r2 = (lane & 3) * 2;
    float2 bv[4];
#pragma unroll
    for (int nt = 0; nt < 4; ++nt)
        bv[nt] = *(const float2*)(bias + bn + wn + nt * 8 + r2);

    float2* red = (float2*)smem;
#pragma unroll
    for (int mt = 0; mt < 4; ++mt) {
        const int row0 = bm + wm + mt * 16 + gq;
        float sA = 0.f, qA = 0.f, sB = 0.f, qB = 0.f;
#pragma unroll
        for (int nt = 0; nt < 4; ++nt) {
            const int col = bn + wn + nt * 8 + r2;
            const float v0x = acc[mt][nt][0] + bv[nt].x;
            const float v0y = acc[mt][nt][1] + bv[nt].y;
            const float v1x = acc[mt][nt][2] + bv[nt].x;
            const float v1y = acc[mt][nt][3] + bv[nt].y;
            *(__half2*)(g_h + (size_t)row0 * DM + col) = __floats2half2_rn(v0x, v0y);
            *(__half2*)(g_h + (size_t)(row0 + 8) * DM + col) = __floats2half2_rn(v1x, v1y);
            sA += v0x + v0y; qA += v0x * v0x + v0y * v0y;
            sB += v1x + v1y; qB += v1x * v1x + v1y * v1y;
        }
#pragma unroll
        for (int o = 1; o <= 2; o <<= 1) {
            sA += __shfl_xor_sync(0xFFFFFFFFu, sA, o);
            qA += __shfl_xor_sync(0xFFFFFFFFu, qA, o);
            sB += __shfl_xor_sync(0xFFFFFFFFu, sB, o);
            qB += __shfl_xor_sync(0xFFFFFFFFu, qB, o);
        }
        if ((lane & 3) == 0) {
            const int lr = wm + mt * 16 + gq;
            red[(wid >> 1) * 128 + lr]     = make_float2(sA, qA);
            red[(wid >> 1) * 128 + lr + 8] = make_float2(sB, qB);
        }
    }
    __syncthreads();
    if (tid < 128) {
        float s = 0.f, q = 0.f;
#pragma unroll
        for (int ns = 0; ns < 4; ++ns) {
            const float2 v = red[ns * 128 + tid];
            s += v.x; q += v.y;
        }
        g_psum[(size_t)(bm + tid) * 4 + blockIdx.x] = s;
        g_psq [(size_t)(bm + tid) * 4 + blockIdx.x] = q;
    }
}

// ===========================================================================
// Kernel 2 (fused): mu/rstd from GEMM partials + chunk sums of normalized h
// + windowed complex S partials (chunks c < NSP).
// grid=(NCH=128,BSZ), 256 threads (channel pairs); prefetched row loads.
// ===========================================================================
__global__ __launch_bounds__(256)
void stat_pass1_kernel(const float* __restrict__ Are, const float* __restrict__ Aim,
                       const float* __restrict__ gamma, const float* __restrict__ beta)
{
    __shared__ float s_mu[CHUNK], s_rs[CHUNK];
    const int tid = threadIdx.x;
    const int c = blockIdx.x;
    const int b = blockIdx.y;
    const size_t row0 = (size_t)b * LSEQ + (size_t)c * CHUNK;

    if (tid < CHUNK) {
        const size_t gr = row0 + tid;
        float s = 0.f, q = 0.f;
#pragma unroll
        for (int ns = 0; ns < 4; ++ns) {
            s += g_psum[gr * 4 + ns];
            q += g_psq[gr * 4 + ns];
        }
        const float mu   = s * (1.0f / DM);
        const float var  = q * (1.0f / DM) - mu * mu;
        const float rstd = rsqrtf(var + 1e-5f);
        s_mu[tid] = mu;  s_rs[tid] = rstd;
        g_mu[gr] = mu;   g_rs[gr] = rstd;
    }
    __syncthreads();

    const int d = tid * 2;
    const float2 gd = *(const float2*)(gamma + d);
    const float2 bd = *(const float2*)(beta + d);
    const __half* p = g_h + row0 * DM + d;

    __half2 hvr[CHUNK];
#pragma unroll
    for (int i = 0; i < CHUNK; ++i)
        hvr[i] = *(const __half2*)(p + (size_t)i * DM);

    if (c < NSP) {
        const float2 are = *(const float2*)(Are + d);
        const float2 aim = *(const float2*)(Aim + d);
        float2 s = make_float2(0.f, 0.f);
        float pre0 = 1.f, pim0 = 0.f, Sre0 = 0.f, Sim0 = 0.f;
        float pre1 = 1.f, pim1 = 0.f, Sre1 = 0.f, Sim1 = 0.f;
#pragma unroll
        for (int i = 0; i < CHUNK; ++i) {
            const float2 hv = __half22float2(hvr[i]);
            const float hn0 = (hv.x - s_mu[i]) * s_rs[i] * gd.x + bd.x;
            const float hn1 = (hv.y - s_mu[i]) * s_rs[i] * gd.y + bd.y;
            s.x += hn0; s.y += hn1;
            Sre0 = fmaf(pre0, hn0, Sre0);  Sim0 = fmaf(pim0, hn0, Sim0);
            Sre1 = fmaf(pre1, hn1, Sre1);  Sim1 = fmaf(pim1, hn1, Sim1);
            float nr = pre0 * are.x - pim0 * aim.x;
            float ni = pre0 * aim.x + pim0 * are.x;
            pre0 = nr; pim0 = ni;
            nr = pre1 * are.y - pim1 * aim.y;
            ni = pre1 * aim.y + pim1 * are.y;
            pre1 = nr; pim1 = ni;
        }
        *(float2*)(g_csum + ((size_t)b * NCH + c) * DM + d) = s;
        float wre0 = 1.f, wim0 = 0.f, wre1 = 1.f, wim1 = 0.f;
        if (c > 0) {
            float t0r = are.x, t0i = aim.x, t1r = are.y, t1i = aim.y;
#pragma unroll
            for (int k = 0; k < 4; ++k) {
                float nr = t0r * t0r - t0i * t0i, ni = 2.f * t0r * t0i;
                t0r = nr; t0i = ni;
                nr = t1r * t1r - t1i * t1i; ni = 2.f * t1r * t1i;
                t1r = nr; t1i = ni;
            }
            for (int j = 0; j < c; ++j) {
                float nr = wre0 * t0r - wim0 * t0i, ni = wre0 * t0i + wim0 * t0r;
                wre0 = nr; wim0 = ni;
                nr = wre1 * t1r - wim1 * t1i; ni = wre1 * t1i + wim1 * t1r;
                wre1 = nr; wim1 = ni;
            }
        }
        float2 oSr, oSi;
        oSr.x = Sre0 * wre0 - Sim0 * wim0;  oSi.x = Sre0 * wim0 + Sim0 * wre0;
        oSr.y = Sre1 * wre1 - Sim1 * wim1;  oSi.y = Sre1 * wim1 + Sim1 * wre1;
        *(float2*)(g_Sre + ((size_t)b * NSP + c) * DM + d) = oSr;
        *(float2*)(g_Sim + ((size_t)b * NSP + c) * DM + d) = oSi;
    } else {
        float s0 = 0.f, s1 = 0.f;
#pragma unroll
        for (int i = 0; i < CHUNK; ++i) {
            const float2 hv = __half22float2(hvr[i]);
            const float w = s_rs[i];
            s0 += (hv.x - s_mu[i]) * w;
            s1 += (hv.y - s_mu[i]) * w;
        }
        float2 out;
        out.x = fmaf(gd.x, s0, (float)CHUNK * bd.x);
        out.y = fmaf(gd.y, s1, (float)CHUNK * bd.y);
        *(float2*)(g_csum + ((size_t)b * NCH + c) * DM + d) = out;
    }
}

// ===========================================================================
// Kernel 2b: in-place exclusive scan of g_csum along c (coalesced, smem).
// grid = (DM/32, BSZ) = 128 blocks x 256 threads. Block: one b, 32 channels,
// all 128 chunks. Coalesced load -> smem scan -> coalesced store.
// ===========================================================================
__global__ __launch_bounds__(256)
void scan_kernel()
{
    __shared__ float sm[NCH * 32];        // [c][dd], 16 KB
    __shared__ float gs[8 * 32];          // per-group totals
    const int t  = threadIdx.x;
    const int b  = blockIdx.y;
    const int d0 = blockIdx.x * 32;
    float* base = g_csum + (size_t)b * NCH * DM + d0;

    // coalesced load: 4096 elements, 16 per thread
#pragma unroll
    for (int k = 0; k < 16; ++k) {
        const int idx = t + k * 256;
        const int c = idx >> 5, dd = idx & 31;
        sm[idx] = base[(size_t)c * DM + dd];
    }
    __syncthreads();

    // local exclusive scan: thread owns dd = t&31, c-group g = t>>5 (16 c's)
    const int dd = t & 31;
    const int g  = t >> 5;
    float run = 0.f;
#pragma unroll
    for (int i = 0; i < 16; ++i) {
        const int c = g * 16 + i;
        const float v = sm[c * 32 + dd];
        sm[c * 32 + dd] = run;
        run += v;
    }
    gs[g * 32 + dd] = run;
    __syncthreads();

    float off = 0.f;
#pragma unroll
    for (int j = 0; j < 8; ++j)
        if (j < g) off += gs[j * 32 + dd];

    // coalesced store of exclusive prefix
#pragma unroll
    for (int i = 0; i < 16; ++i) {
        const int c = g * 16 + i;
        base[(size_t)c * DM + dd] = sm[c * 32 + dd] + off;
    }
}

// ===========================================================================
// Kernel 3: y[l] = hn[l] + ReDc*prefix(hn)[l]; last chunk adds tail.
// Offset = single exclusive-prefix load. grid = (NCH=128, BSZ), 256 threads.
// ===========================================================================
__global__ __launch_bounds__(256)
void pass2_kernel(float* __restrict__ Y,
                  const float* __restrict__ Are, const float* __restrict__ Aim,
                  const float* __restrict__ Bre, const float* __restrict__ Bim,
                  const float* __restrict__ Cre, const float* __restrict__ Cim,
                  const float* __restrict__ Dre,
                  const float* __restrict__ gamma, const float* __restrict__ beta)
{
    __shared__ float s_mu[CHUNK], s_rs[CHUNK];
    const int tid = threadIdx.x;
    const int c = blockIdx.x;
    const int b = blockIdx.y;
    const size_t row0 = (size_t)b * LSEQ + (size_t)c * CHUNK;

    if (tid < CHUNK) {
        s_mu[tid] = g_mu[row0 + tid];
        s_rs[tid] = g_rs[row0 + tid];
    }
    __syncthreads();

    const int d = tid * 2;
    float2 run = *(const float2*)(g_csum + ((size_t)b * NCH + c) * DM + d);

    const size_t base = row0 * DM + d;
    const float2 gd = *(const float2*)(gamma + d);
    const float2 bd = *(const float2*)(beta + d);
    const float2 dre = *(const float2*)(Dre + d);

    __half2 hvr[CHUNK];
#pragma unroll
    for (int i = 0; i < CHUNK; ++i)
        hvr[i] = *(const __half2*)(g_h + base + (size_t)i * DM);

    if (c < NCH - 1) {
#pragma unroll
        for (int i = 0; i < CHUNK; ++i) {
            const float2 hv = __half22float2(hvr[i]);
            const float hn0 = (hv.x - s_mu[i]) * s_rs[i] * gd.x + bd.x;
            const float hn1 = (hv.y - s_mu[i]) * s_rs[i] * gd.y + bd.y;
            run.x += hn0; run.y += hn1;
            float2 out;
            out.x = fmaf(dre.x, run.x, hn0);
            out.y = fmaf(dre.y, run.y, hn1);
            *(float2*)(Y + base + (size_t)i * DM) = out;
        }
    } else {
        const float2 are = *(const float2*)(Are + d);
        const float2 aim = *(const float2*)(Aim + d);
        const float2 bre = *(const float2*)(Bre + d);
        const float2 bim = *(const float2*)(Bim + d);
        const float2 cre = *(const float2*)(Cre + d);
        const float2 cim = *(const float2*)(Cim + d);
        const float bcre0 = bre.x * cre.x - bim.x * cim.x;
        const float bcim0 = bre.x * cim.x + bim.x * cre.x;
        const float bcre1 = bre.y * cre.y - bim.y * cim.y;
        const float bcim1 = bre.y * cim.y + bim.y * cre.y;
        float2 Sre = make_float2(0.f, 0.f), Sim = make_float2(0.f, 0.f);
#pragma unroll
        for (int j = 0; j < NSP; ++j) {
            const float2 vr = *(const float2*)(g_Sre + ((size_t)b * NSP + j) * DM + d);
            const float2 vi = *(const float2*)(g_Sim + ((size_t)b * NSP + j) * DM + d);
            Sre.x += vr.x; Sre.y += vr.y;
            Sim.x += vi.x; Sim.y += vi.y;
        }
        float t0[CHUNK], t1[CHUNK];
        float q0r = 1.f, q0i = 0.f, q1r = 1.f, q1i = 0.f;
#pragma unroll
        for (int i = CHUNK - 1; i >= 0; --i) {
            const float z0r = q0r * Sre.x - q0i * Sim.x;
            const float z0i = q0r * Sim.x + q0i * Sre.x;
            const float z1r = q1r * Sre.y - q1i * Sim.y;
            const float z1i = q1r * Sim.y + q1i * Sre.y;
            t0[i] = bcre0 * z0r - bcim0 * z0i;
            t1[i] = bcre1 * z1r - bcim1 * z1i;
            float nr = q0r * are.x - q0i * aim.x, ni = q0r * aim.x + q0i * are.x;
            q0r = nr; q0i = ni;
            nr = q1r * are.y - q1i * aim.y; ni = q1r * aim.y + q1i * are.y;
            q1r = nr; q1i = ni;
        }
#pragma unroll
        for (int i = 0; i < CHUNK; ++i) {
            const float2 hv = __half22float2(hvr[i]);
            const float hn0 = (hv.x - s_mu[i]) * s_rs[i] * gd.x + bd.x;
            const float hn1 = (hv.y - s_mu[i]) * s_rs[i] * gd.y + bd.y;
            run.x += hn0; run.y += hn1;
            float2 out;
            out.x = fmaf(dre.x, run.x, hn0) + t0[i];
            out.y = fmaf(dre.y, run.y, hn1) + t1[i];
            *(float2*)(Y + base + (size_t)i * DM) = out;
        }
    }
}

// ---------------------------------------------------------------------------
extern "C" void kernel_launch(void* const* d_in, const int* in_sizes, int n_in,
                              void* d_out, int out_size)
{
    const float* x    = (const float*)d_in[0];
    const float* Are  = (const float*)d_in[1];
    const float* Aim  = (const float*)d_in[2];
    const float* Bre  = (const float*)d_in[3];
    const float* Bim  = (const float*)d_in[4];
    const float* Cre  = (const float*)d_in[5];
    const float* Cim  = (const float*)d_in[6];
    const float* Dre  = (const float*)d_in[7];
    const float* W    = (const float*)d_in[9];
    const float* bias = (const float*)d_in[10];
    const float* gamma= (const float*)d_in[11];
    const float* beta = (const float*)d_in[12];
    float* out = (float*)d_out;

    cudaFuncSetAttribute(gemm_mma_kernel,
                         cudaFuncAttributeMaxDynamicSharedMemorySize, SMEM_G);
    cvt_kernel<<<N4T / 256, 256>>>(x, W);
    gemm_mma_kernel<<<dim3(DM / 128, MTOT / 128), 256, SMEM_G>>>(bias);
    stat_pass1_kernel<<<dim3(NCH, BSZ), 256>>>(Are, Aim, gamma, beta);
    scan_kernel<<<dim3(DM / 32, BSZ), 256>>>();
    pass2_kernel<<<dim3(NCH, BSZ), 256>>>(out, Are, Aim, Bre, Bim, Cre, Cim, Dre,
                                          gamma, beta);
}